// round 6
// baseline (speedup 1.0000x reference)
#include <cuda_runtime.h>

#define DIMC 1024
#define NHEAD 16
#define HDIM 64
#define BATCH 4
#define SEQ 2048
#define MTOT (BATCH*SEQ)
#define NQKV (3*DIMC)

// g_qkv holds TF32 bit patterns (pre-converted in qkv-GEMM epilogue)
__device__ unsigned g_qkv[(size_t)3*BATCH*NHEAD*SEQ*HDIM];   // [3][B][H][S][D]
__device__ float    g_attn[(size_t)MTOT*DIMC];               // [B*S][C]

__device__ __forceinline__ unsigned f2tf(float x){
    unsigned r; asm("cvt.rna.tf32.f32 %0,%1;" : "=r"(r) : "f"(x)); return r;
}

__device__ __forceinline__ void mma8(float* c, const unsigned* a, const unsigned* b){
    asm volatile(
      "mma.sync.aligned.m16n8k8.row.col.f32.tf32.tf32.f32 "
      "{%0,%1,%2,%3},{%4,%5,%6,%7},{%8,%9},{%0,%1,%2,%3};\n"
      : "+f"(c[0]),"+f"(c[1]),"+f"(c[2]),"+f"(c[3])
      : "r"(a[0]),"r"(a[1]),"r"(a[2]),"r"(a[3]),"r"(b[0]),"r"(b[1]));
}

// ---------------------------------------------------------------------------
// Tensor-core GEMM (R2 version): C = A[M,1024] @ B[1024,N] + bias
// 128x128x16 tiles, double-buffered, tf32 in smem.
// SCATTER=true: epilogue stores TF32 bits into g_qkv [3][B][H][S][D]
// SCATTER=false: reads g_attn, writes fp32 out + bias
// ---------------------------------------------------------------------------
#define ASTR 136
#define BSTR 136

template<int N, bool SCATTER>
__global__ __launch_bounds__(256)
void gemm_mma(const float* __restrict__ A, const float* __restrict__ B,
              const float* __restrict__ bias, float* __restrict__ out)
{
    __shared__ unsigned As[2][16*ASTR];
    __shared__ unsigned Bs[2][16*BSTR];
    const int tid=threadIdx.x, lane=tid&31, warp=tid>>5;
    const int g=lane>>2, tg=lane&3;
    const int mbase=(warp>>2)*64, nbase=(warp&3)*32;
    const int bm=blockIdx.y*128, bn=blockIdx.x*128;
    const float* Asrc = SCATTER ? A : (const float*)g_attn;
    const float* Ab = Asrc + (size_t)bm*DIMC;
    const float* Bb = B + bn;

    float4 ar[2], br[2];
    float acc[4][4][4];
    #pragma unroll
    for(int i=0;i<4;i++)
      #pragma unroll
      for(int j=0;j<4;j++)
        #pragma unroll
        for(int k=0;k<4;k++) acc[i][j][k]=0.f;

    const int NT = DIMC/16;

    #pragma unroll
    for(int i=0;i<2;i++){
        int idx=tid+(i<<8);
        ar[i]=*(const float4*)(Ab + (size_t)(idx>>2)*DIMC + ((idx&3)<<2));
        br[i]=*(const float4*)(Bb + (size_t)(idx>>5)*N + ((idx&31)<<2));
    }
    #pragma unroll
    for(int i=0;i<2;i++){
        int idx=tid+(i<<8);
        int r=idx>>2, kc=(idx&3)<<2;
        As[0][(kc+0)*ASTR+r]=f2tf(ar[i].x);
        As[0][(kc+1)*ASTR+r]=f2tf(ar[i].y);
        As[0][(kc+2)*ASTR+r]=f2tf(ar[i].z);
        As[0][(kc+3)*ASTR+r]=f2tf(ar[i].w);
        int rb=idx>>5, cb=(idx&31)<<2;
        unsigned* p=&Bs[0][rb*BSTR+cb];
        p[0]=f2tf(br[i].x); p[1]=f2tf(br[i].y); p[2]=f2tf(br[i].z); p[3]=f2tf(br[i].w);
    }
    __syncthreads();

    for(int kt=0;kt<NT;kt++){
        const int buf=kt&1;
        if(kt<NT-1){
            #pragma unroll
            for(int i=0;i<2;i++){
                int idx=tid+(i<<8);
                ar[i]=*(const float4*)(Ab + (size_t)(idx>>2)*DIMC + (kt+1)*16 + ((idx&3)<<2));
                br[i]=*(const float4*)(Bb + (size_t)((kt+1)*16+(idx>>5))*N + ((idx&31)<<2));
            }
        }
        #pragma unroll
        for(int ks=0;ks<2;ks++){
            const int k0=ks*8;
            unsigned af[4][4], bf[4][2];
            #pragma unroll
            for(int mi=0;mi<4;mi++){
                const int m0=mbase+mi*16;
                af[mi][0]=As[buf][(k0+tg)*ASTR+m0+g];
                af[mi][1]=As[buf][(k0+tg)*ASTR+m0+g+8];
                af[mi][2]=As[buf][(k0+tg+4)*ASTR+m0+g];
                af[mi][3]=As[buf][(k0+tg+4)*ASTR+m0+g+8];
            }
            #pragma unroll
            for(int ni=0;ni<4;ni++){
                const int n0=nbase+ni*8;
                bf[ni][0]=Bs[buf][(k0+tg)*BSTR+n0+g];
                bf[ni][1]=Bs[buf][(k0+tg+4)*BSTR+n0+g];
            }
            #pragma unroll
            for(int mi=0;mi<4;mi++)
                #pragma unroll
                for(int ni=0;ni<4;ni++)
                    mma8(acc[mi][ni],af[mi],bf[ni]);
        }
        if(kt<NT-1){
            #pragma unroll
            for(int i=0;i<2;i++){
                int idx=tid+(i<<8);
                int r=idx>>2, kc=(idx&3)<<2;
                As[buf^1][(kc+0)*ASTR+r]=f2tf(ar[i].x);
                As[buf^1][(kc+1)*ASTR+r]=f2tf(ar[i].y);
                As[buf^1][(kc+2)*ASTR+r]=f2tf(ar[i].z);
                As[buf^1][(kc+3)*ASTR+r]=f2tf(ar[i].w);
                int rb=idx>>5, cb=(idx&31)<<2;
                unsigned* p=&Bs[buf^1][rb*BSTR+cb];
                p[0]=f2tf(br[i].x); p[1]=f2tf(br[i].y); p[2]=f2tf(br[i].z); p[3]=f2tf(br[i].w);
            }
        }
        __syncthreads();
    }

    #pragma unroll
    for(int mi=0;mi<4;mi++){
        #pragma unroll
        for(int ni=0;ni<4;ni++){
            #pragma unroll
            for(int e=0;e<4;e++){
                const int r = bm + mbase + mi*16 + g + ((e>=2)?8:0);
                const int c = bn + nbase + ni*8 + 2*tg + (e&1);
                const float v = acc[mi][ni][e] + bias[c];
                if(SCATTER){
                    const int b=r>>11, s=r&2047;
                    const int t=c>>10, h=(c>>6)&15, d=c&63;
                    g_qkv[((((size_t)t*BATCH+b)*NHEAD+h)*SEQ+s)*HDIM+d]=f2tf(v);
                } else {
                    out[(size_t)r*N+c]=v;
                }
            }
        }
    }
}

// ---------------------------------------------------------------------------
// Flash attention: q-tile 128, 256 threads (8 warps x 16 q-rows), k-tile 64.
// g_qkv already TF32 — fills are pure LDG.128 -> STS.128 (no cvt).
// Per-warp mainloop identical to the proven R2 version.
// ---------------------------------------------------------------------------
#define QKOFF ((size_t)BATCH*NHEAD*SEQ*HDIM)
#define FSTR 68
#define FLASH_SMEM ((128*FSTR + 2*64*FSTR + 8*1024)*4)   /* 102400 B */

__global__ __launch_bounds__(256,2)
void flash_mma()
{
    extern __shared__ __align__(16) unsigned sm[];
    unsigned* Qs=sm;                  // 128 x FSTR
    unsigned* Ks=Qs+128*FSTR;         // 64 x FSTR
    unsigned* Vs=Ks+64*FSTR;          // 64 x FSTR
    unsigned* Ps=Vs+64*FSTR;          // 8 x 1024
    const int tid=threadIdx.x, lane=tid&31, warp=tid>>5;
    const int g=lane>>2, tg=lane&3;
    const int qb=warp*16;
    const int b=blockIdx.y>>4, h=blockIdx.y&15;
    const int q0=blockIdx.x*128;
    const unsigned* Qg=g_qkv + ((size_t)(b*NHEAD+h))*SEQ*HDIM;
    const unsigned* Kg=Qg + QKOFF;
    const unsigned* Vg=Kg + QKOFF;
    unsigned* Pw = Ps + warp*1024;

    #pragma unroll
    for(int i=0;i<8;i++){
        int idx=tid+(i<<8);
        int r=idx>>4, c=(idx&15)<<2;
        *(uint4*)&Qs[r*FSTR+c] = *(const uint4*)(Qg+(size_t)(q0+r)*HDIM+c);
    }

    float oc[8][4];
    #pragma unroll
    for(int i=0;i<8;i++)
        #pragma unroll
        for(int j=0;j<4;j++) oc[i][j]=0.f;
    float m0=-1e30f, m1=-1e30f, l0=0.f, l1=0.f;
    const float scale=0.125f;

    for(int kt=0;kt<SEQ/64;kt++){
        __syncthreads();   // prev iteration done with Ks/Vs
        #pragma unroll
        for(int i=0;i<4;i++){
            int idx=tid+(i<<8);
            int r=idx>>4, c=(idx&15)<<2;
            *(uint4*)&Ks[r*FSTR+c] = *(const uint4*)(Kg+(size_t)(kt*64+r)*HDIM+c);
            *(uint4*)&Vs[r*FSTR+c] = *(const uint4*)(Vg+(size_t)(kt*64+r)*HDIM+c);
        }
        __syncthreads();

        // S = Q @ K^T
        float sc[8][4];
        #pragma unroll
        for(int i=0;i<8;i++)
            #pragma unroll
            for(int j=0;j<4;j++) sc[i][j]=0.f;
        #pragma unroll
        for(int ks=0;ks<8;ks++){
            const int k0=ks*8;
            unsigned af[4];
            af[0]=Qs[(qb+g  )*FSTR+k0+tg];
            af[1]=Qs[(qb+g+8)*FSTR+k0+tg];
            af[2]=Qs[(qb+g  )*FSTR+k0+tg+4];
            af[3]=Qs[(qb+g+8)*FSTR+k0+tg+4];
            #pragma unroll
            for(int ni=0;ni<8;ni++){
                unsigned bf[2];
                bf[0]=Ks[(ni*8+g)*FSTR+k0+tg];
                bf[1]=Ks[(ni*8+g)*FSTR+k0+tg+4];
                mma8(sc[ni],af,bf);
            }
        }

        // online softmax
        float mx0=-1e30f, mx1=-1e30f;
        #pragma unroll
        for(int ni=0;ni<8;ni++){
            sc[ni][0]*=scale; sc[ni][1]*=scale; sc[ni][2]*=scale; sc[ni][3]*=scale;
            mx0=fmaxf(mx0,fmaxf(sc[ni][0],sc[ni][1]));
            mx1=fmaxf(mx1,fmaxf(sc[ni][2],sc[ni][3]));
        }
        mx0=fmaxf(mx0,__shfl_xor_sync(0xffffffffu,mx0,1));
        mx0=fmaxf(mx0,__shfl_xor_sync(0xffffffffu,mx0,2));
        mx1=fmaxf(mx1,__shfl_xor_sync(0xffffffffu,mx1,1));
        mx1=fmaxf(mx1,__shfl_xor_sync(0xffffffffu,mx1,2));
        const float nm0=fmaxf(m0,mx0), nm1=fmaxf(m1,mx1);
        const float a0=__expf(m0-nm0), a1=__expf(m1-nm1);
        m0=nm0; m1=nm1;
        float s0=0.f, s1=0.f;
        #pragma unroll
        for(int ni=0;ni<8;ni++){
            sc[ni][0]=__expf(sc[ni][0]-nm0); sc[ni][1]=__expf(sc[ni][1]-nm0);
            sc[ni][2]=__expf(sc[ni][2]-nm1); sc[ni][3]=__expf(sc[ni][3]-nm1);
            s0+=sc[ni][0]+sc[ni][1];
            s1+=sc[ni][2]+sc[ni][3];
        }
        s0+=__shfl_xor_sync(0xffffffffu,s0,1); s0+=__shfl_xor_sync(0xffffffffu,s0,2);
        s1+=__shfl_xor_sync(0xffffffffu,s1,1); s1+=__shfl_xor_sync(0xffffffffu,s1,2);
        l0=l0*a0+s0; l1=l1*a1+s1;

        // P -> per-warp fragment buffer
        #pragma unroll
        for(int ni=0;ni<8;ni++){
            unsigned* pp=&Pw[(ni*32 + g*4 + ((2*tg)&3))*4 + 2*(tg>>1)];
            *(uint2*)pp    =make_uint2(f2tf(sc[ni][0]), f2tf(sc[ni][2]));
            *(uint2*)(pp+4)=make_uint2(f2tf(sc[ni][1]), f2tf(sc[ni][3]));
        }
        __syncwarp();

        #pragma unroll
        for(int di=0;di<8;di++){
            oc[di][0]*=a0; oc[di][1]*=a0; oc[di][2]*=a1; oc[di][3]*=a1;
        }
        // O += P @ V
        #pragma unroll
        for(int ks=0;ks<8;ks++){
            uint4 af4=*(const uint4*)&Pw[ks*128 + lane*4];
            const unsigned* AF=(const unsigned*)&af4;
            const int k0=ks*8;
            #pragma unroll
            for(int di=0;di<8;di++){
                unsigned bf[2];
                bf[0]=Vs[(k0+tg  )*FSTR+di*8+g];
                bf[1]=Vs[(k0+tg+4)*FSTR+di*8+g];
                mma8(oc[di],AF,bf);
            }
        }
        __syncwarp();
    }

    const float i0=1.f/l0, i1=1.f/l1;
    const int r0=q0+qb+g, r1=r0+8;
    float* O0=&g_attn[((size_t)(b*SEQ)+r0)*DIMC + h*HDIM];
    float* O1=&g_attn[((size_t)(b*SEQ)+r1)*DIMC + h*HDIM];
    #pragma unroll
    for(int di=0;di<8;di++){
        const int c=di*8+2*tg;
        *(float2*)&O0[c]=make_float2(oc[di][0]*i0, oc[di][1]*i0);
        *(float2*)&O1[c]=make_float2(oc[di][2]*i1, oc[di][3]*i1);
    }
}

// ---------------------------------------------------------------------------
extern "C" void kernel_launch(void* const* d_in, const int* in_sizes, int n_in,
                              void* d_out, int out_size)
{
    const float* x     = (const float*)d_in[0];
    const float* Wqkv  = (const float*)d_in[1];
    const float* bqkv  = (const float*)d_in[2];
    const float* Wproj = (const float*)d_in[3];
    const float* bproj = (const float*)d_in[4];
    float* out = (float*)d_out;

    cudaFuncSetAttribute(flash_mma, cudaFuncAttributeMaxDynamicSharedMemorySize, FLASH_SMEM);

    dim3 g1(NQKV/128, MTOT/128);   // (24, 64)
    gemm_mma<NQKV, true><<<g1, 256>>>(x, Wqkv, bqkv, nullptr);

    dim3 g2(SEQ/128, BATCH*NHEAD); // (16, 64)
    flash_mma<<<g2, 256, FLASH_SMEM>>>();

    dim3 g3(DIMC/128, MTOT/128);   // (8, 64)
    gemm_mma<DIMC, false><<<g3, 256>>>(nullptr, Wproj, bproj, out);
}

// round 7
// speedup vs baseline: 1.4841x; 1.4841x over previous
#include <cuda_runtime.h>

#define DIMC 1024
#define NHEAD 16
#define HDIM 64
#define BATCH 4
#define SEQ 2048
#define MTOT (BATCH*SEQ)
#define NQKV (3*DIMC)

// g_qkv holds TF32 bit patterns (pre-converted in qkv-GEMM epilogue)
__device__ unsigned g_qkv[(size_t)3*BATCH*NHEAD*SEQ*HDIM];   // [3][B][H][S][D]
__device__ float    g_attn[(size_t)MTOT*DIMC];               // [B*S][C]

__device__ __forceinline__ unsigned f2tf(float x){
    unsigned r; asm("cvt.rna.tf32.f32 %0,%1;" : "=r"(r) : "f"(x)); return r;
}

__device__ __forceinline__ void mma8(float* c, const unsigned* a, const unsigned* b){
    asm volatile(
      "mma.sync.aligned.m16n8k8.row.col.f32.tf32.tf32.f32 "
      "{%0,%1,%2,%3},{%4,%5,%6,%7},{%8,%9},{%0,%1,%2,%3};\n"
      : "+f"(c[0]),"+f"(c[1]),"+f"(c[2]),"+f"(c[3])
      : "r"(a[0]),"r"(a[1]),"r"(a[2]),"r"(a[3]),"r"(b[0]),"r"(b[1]));
}

// ---------------------------------------------------------------------------
// Tensor-core GEMM (R2 version): C = A[M,1024] @ B[1024,N] + bias
// 128x128x16 tiles, double-buffered, tf32 in smem.
// SCATTER=true: epilogue stores TF32 bits into g_qkv [3][B][H][S][D]
// SCATTER=false: reads g_attn, writes fp32 out + bias
// ---------------------------------------------------------------------------
#define ASTR 136
#define BSTR 136

template<int N, bool SCATTER>
__global__ __launch_bounds__(256)
void gemm_mma(const float* __restrict__ A, const float* __restrict__ B,
              const float* __restrict__ bias, float* __restrict__ out)
{
    __shared__ unsigned As[2][16*ASTR];
    __shared__ unsigned Bs[2][16*BSTR];
    const int tid=threadIdx.x, lane=tid&31, warp=tid>>5;
    const int g=lane>>2, tg=lane&3;
    const int mbase=(warp>>2)*64, nbase=(warp&3)*32;
    const int bm=blockIdx.y*128, bn=blockIdx.x*128;
    const float* Asrc = SCATTER ? A : (const float*)g_attn;
    const float* Ab = Asrc + (size_t)bm*DIMC;
    const float* Bb = B + bn;

    float4 ar[2], br[2];
    float acc[4][4][4];
    #pragma unroll
    for(int i=0;i<4;i++)
      #pragma unroll
      for(int j=0;j<4;j++)
        #pragma unroll
        for(int k=0;k<4;k++) acc[i][j][k]=0.f;

    const int NT = DIMC/16;

    #pragma unroll
    for(int i=0;i<2;i++){
        int idx=tid+(i<<8);
        ar[i]=*(const float4*)(Ab + (size_t)(idx>>2)*DIMC + ((idx&3)<<2));
        br[i]=*(const float4*)(Bb + (size_t)(idx>>5)*N + ((idx&31)<<2));
    }
    #pragma unroll
    for(int i=0;i<2;i++){
        int idx=tid+(i<<8);
        int r=idx>>2, kc=(idx&3)<<2;
        As[0][(kc+0)*ASTR+r]=f2tf(ar[i].x);
        As[0][(kc+1)*ASTR+r]=f2tf(ar[i].y);
        As[0][(kc+2)*ASTR+r]=f2tf(ar[i].z);
        As[0][(kc+3)*ASTR+r]=f2tf(ar[i].w);
        int rb=idx>>5, cb=(idx&31)<<2;
        unsigned* p=&Bs[0][rb*BSTR+cb];
        p[0]=f2tf(br[i].x); p[1]=f2tf(br[i].y); p[2]=f2tf(br[i].z); p[3]=f2tf(br[i].w);
    }
    __syncthreads();

    for(int kt=0;kt<NT;kt++){
        const int buf=kt&1;
        if(kt<NT-1){
            #pragma unroll
            for(int i=0;i<2;i++){
                int idx=tid+(i<<8);
                ar[i]=*(const float4*)(Ab + (size_t)(idx>>2)*DIMC + (kt+1)*16 + ((idx&3)<<2));
                br[i]=*(const float4*)(Bb + (size_t)((kt+1)*16+(idx>>5))*N + ((idx&31)<<2));
            }
        }
        #pragma unroll
        for(int ks=0;ks<2;ks++){
            const int k0=ks*8;
            unsigned af[4][4], bf[4][2];
            #pragma unroll
            for(int mi=0;mi<4;mi++){
                const int m0=mbase+mi*16;
                af[mi][0]=As[buf][(k0+tg)*ASTR+m0+g];
                af[mi][1]=As[buf][(k0+tg)*ASTR+m0+g+8];
                af[mi][2]=As[buf][(k0+tg+4)*ASTR+m0+g];
                af[mi][3]=As[buf][(k0+tg+4)*ASTR+m0+g+8];
            }
            #pragma unroll
            for(int ni=0;ni<4;ni++){
                const int n0=nbase+ni*8;
                bf[ni][0]=Bs[buf][(k0+tg)*BSTR+n0+g];
                bf[ni][1]=Bs[buf][(k0+tg+4)*BSTR+n0+g];
            }
            #pragma unroll
            for(int mi=0;mi<4;mi++)
                #pragma unroll
                for(int ni=0;ni<4;ni++)
                    mma8(acc[mi][ni],af[mi],bf[ni]);
        }
        if(kt<NT-1){
            #pragma unroll
            for(int i=0;i<2;i++){
                int idx=tid+(i<<8);
                int r=idx>>2, kc=(idx&3)<<2;
                As[buf^1][(kc+0)*ASTR+r]=f2tf(ar[i].x);
                As[buf^1][(kc+1)*ASTR+r]=f2tf(ar[i].y);
                As[buf^1][(kc+2)*ASTR+r]=f2tf(ar[i].z);
                As[buf^1][(kc+3)*ASTR+r]=f2tf(ar[i].w);
                int rb=idx>>5, cb=(idx&31)<<2;
                unsigned* p=&Bs[buf^1][rb*BSTR+cb];
                p[0]=f2tf(br[i].x); p[1]=f2tf(br[i].y); p[2]=f2tf(br[i].z); p[3]=f2tf(br[i].w);
            }
        }
        __syncthreads();
    }

    #pragma unroll
    for(int mi=0;mi<4;mi++){
        #pragma unroll
        for(int ni=0;ni<4;ni++){
            #pragma unroll
            for(int e=0;e<4;e++){
                const int r = bm + mbase + mi*16 + g + ((e>=2)?8:0);
                const int c = bn + nbase + ni*8 + 2*tg + (e&1);
                const float v = acc[mi][ni][e] + bias[c];
                if(SCATTER){
                    const int b=r>>11, s=r&2047;
                    const int t=c>>10, h=(c>>6)&15, d=c&63;
                    g_qkv[((((size_t)t*BATCH+b)*NHEAD+h)*SEQ+s)*HDIM+d]=f2tf(v);
                } else {
                    out[(size_t)r*N+c]=v;
                }
            }
        }
    }
}

// ---------------------------------------------------------------------------
// Flash attention (R2 structure): 128 thr, q-tile 64, k-tile 64.
// g_qkv already TF32 — Q/K/V fills are pure uint4 copies (no cvt).
// ---------------------------------------------------------------------------
#define QKOFF ((size_t)BATCH*NHEAD*SEQ*HDIM)
#define FSTR 68
#define FLASH_SMEM (4*64*FSTR*4)   /* 69632 B */

__global__ __launch_bounds__(128)
void flash_mma()
{
    extern __shared__ __align__(16) unsigned sm[];
    unsigned* Qs=sm;
    unsigned* Ks=Qs+64*FSTR;
    unsigned* Vs=Ks+64*FSTR;
    unsigned* Ps=Vs+64*FSTR;
    const int tid=threadIdx.x, lane=tid&31, warp=tid>>5;
    const int g=lane>>2, tg=lane&3;
    const int qb=warp*16;
    const int b=blockIdx.y>>4, h=blockIdx.y&15;
    const int q0=blockIdx.x*64;
    const unsigned* Qg=g_qkv + ((size_t)(b*NHEAD+h))*SEQ*HDIM;
    const unsigned* Kg=Qg + QKOFF;
    const unsigned* Vg=Kg + QKOFF;
    unsigned* Pw = Ps + warp*1024;

    #pragma unroll
    for(int i=0;i<8;i++){
        int idx=tid+(i<<7);
        int r=idx>>4, c=(idx&15)<<2;
        *(uint4*)&Qs[r*FSTR+c] = *(const uint4*)(Qg+(size_t)(q0+r)*HDIM+c);
    }

    float oc[8][4];
    #pragma unroll
    for(int i=0;i<8;i++)
        #pragma unroll
        for(int j=0;j<4;j++) oc[i][j]=0.f;
    float m0=-1e30f, m1=-1e30f, l0=0.f, l1=0.f;
    const float scale=0.125f;

    for(int kt=0;kt<SEQ/64;kt++){
        __syncthreads();   // prev iteration done with Ks/Vs (covers Qs on iter 0)
        #pragma unroll
        for(int i=0;i<8;i++){
            int idx=tid+(i<<7);
            int r=idx>>4, c=(idx&15)<<2;
            *(uint4*)&Ks[r*FSTR+c] = *(const uint4*)(Kg+(size_t)(kt*64+r)*HDIM+c);
            *(uint4*)&Vs[r*FSTR+c] = *(const uint4*)(Vg+(size_t)(kt*64+r)*HDIM+c);
        }
        __syncthreads();

        // S = Q @ K^T
        float sc[8][4];
        #pragma unroll
        for(int i=0;i<8;i++)
            #pragma unroll
            for(int j=0;j<4;j++) sc[i][j]=0.f;
        #pragma unroll
        for(int ks=0;ks<8;ks++){
            const int k0=ks*8;
            unsigned af[4];
            af[0]=Qs[(qb+g  )*FSTR+k0+tg];
            af[1]=Qs[(qb+g+8)*FSTR+k0+tg];
            af[2]=Qs[(qb+g  )*FSTR+k0+tg+4];
            af[3]=Qs[(qb+g+8)*FSTR+k0+tg+4];
            #pragma unroll
            for(int ni=0;ni<8;ni++){
                unsigned bf[2];
                bf[0]=Ks[(ni*8+g)*FSTR+k0+tg];
                bf[1]=Ks[(ni*8+g)*FSTR+k0+tg+4];
                mma8(sc[ni],af,bf);
            }
        }

        // online softmax
        float mx0=-1e30f, mx1=-1e30f;
        #pragma unroll
        for(int ni=0;ni<8;ni++){
            sc[ni][0]*=scale; sc[ni][1]*=scale; sc[ni][2]*=scale; sc[ni][3]*=scale;
            mx0=fmaxf(mx0,fmaxf(sc[ni][0],sc[ni][1]));
            mx1=fmaxf(mx1,fmaxf(sc[ni][2],sc[ni][3]));
        }
        mx0=fmaxf(mx0,__shfl_xor_sync(0xffffffffu,mx0,1));
        mx0=fmaxf(mx0,__shfl_xor_sync(0xffffffffu,mx0,2));
        mx1=fmaxf(mx1,__shfl_xor_sync(0xffffffffu,mx1,1));
        mx1=fmaxf(mx1,__shfl_xor_sync(0xffffffffu,mx1,2));
        const float nm0=fmaxf(m0,mx0), nm1=fmaxf(m1,mx1);
        const float a0=__expf(m0-nm0), a1=__expf(m1-nm1);
        m0=nm0; m1=nm1;
        float s0=0.f, s1=0.f;
        #pragma unroll
        for(int ni=0;ni<8;ni++){
            sc[ni][0]=__expf(sc[ni][0]-nm0); sc[ni][1]=__expf(sc[ni][1]-nm0);
            sc[ni][2]=__expf(sc[ni][2]-nm1); sc[ni][3]=__expf(sc[ni][3]-nm1);
            s0+=sc[ni][0]+sc[ni][1];
            s1+=sc[ni][2]+sc[ni][3];
        }
        s0+=__shfl_xor_sync(0xffffffffu,s0,1); s0+=__shfl_xor_sync(0xffffffffu,s0,2);
        s1+=__shfl_xor_sync(0xffffffffu,s1,1); s1+=__shfl_xor_sync(0xffffffffu,s1,2);
        l0=l0*a0+s0; l1=l1*a1+s1;

        // P -> per-warp fragment buffer
        #pragma unroll
        for(int ni=0;ni<8;ni++){
            unsigned* pp=&Pw[(ni*32 + g*4 + ((2*tg)&3))*4 + 2*(tg>>1)];
            *(uint2*)pp    =make_uint2(f2tf(sc[ni][0]), f2tf(sc[ni][2]));
            *(uint2*)(pp+4)=make_uint2(f2tf(sc[ni][1]), f2tf(sc[ni][3]));
        }
        __syncwarp();

        #pragma unroll
        for(int di=0;di<8;di++){
            oc[di][0]*=a0; oc[di][1]*=a0; oc[di][2]*=a1; oc[di][3]*=a1;
        }
        // O += P @ V
        #pragma unroll
        for(int ks=0;ks<8;ks++){
            uint4 af4=*(const uint4*)&Pw[ks*128 + lane*4];
            const unsigned* AF=(const unsigned*)&af4;
            const int k0=ks*8;
            #pragma unroll
            for(int di=0;di<8;di++){
                unsigned bf[2];
                bf[0]=Vs[(k0+tg  )*FSTR+di*8+g];
                bf[1]=Vs[(k0+tg+4)*FSTR+di*8+g];
                mma8(oc[di],AF,bf);
            }
        }
        __syncwarp();
    }

    const float i0=1.f/l0, i1=1.f/l1;
    const int r0=q0+qb+g, r1=r0+8;
    float* O0=&g_attn[((size_t)(b*SEQ)+r0)*DIMC + h*HDIM];
    float* O1=&g_attn[((size_t)(b*SEQ)+r1)*DIMC + h*HDIM];
    #pragma unroll
    for(int di=0;di<8;di++){
        const int c=di*8+2*tg;
        *(float2*)&O0[c]=make_float2(oc[di][0]*i0, oc[di][1]*i0);
        *(float2*)&O1[c]=make_float2(oc[di][2]*i1, oc[di][3]*i1);
    }
}

// ---------------------------------------------------------------------------
extern "C" void kernel_launch(void* const* d_in, const int* in_sizes, int n_in,
                              void* d_out, int out_size)
{
    const float* x     = (const float*)d_in[0];
    const float* Wqkv  = (const float*)d_in[1];
    const float* bqkv  = (const float*)d_in[2];
    const float* Wproj = (const float*)d_in[3];
    const float* bproj = (const float*)d_in[4];
    float* out = (float*)d_out;

    cudaFuncSetAttribute(flash_mma, cudaFuncAttributeMaxDynamicSharedMemorySize, FLASH_SMEM);

    dim3 g1(NQKV/128, MTOT/128);   // (24, 64)
    gemm_mma<NQKV, true><<<g1, 256>>>(x, Wqkv, bqkv, nullptr);

    dim3 g2(SEQ/64, BATCH*NHEAD);  // (32, 64)
    flash_mma<<<g2, 128, FLASH_SMEM>>>();

    dim3 g3(DIMC/128, MTOT/128);   // (8, 64)
    gemm_mma<DIMC, false><<<g3, 256>>>(nullptr, Wproj, bproj, out);
}

// round 8
// speedup vs baseline: 1.5370x; 1.0357x over previous
#include <cuda_runtime.h>

#define DIMC 1024
#define NHEAD 16
#define HDIM 64
#define BATCH 4
#define SEQ 2048
#define MTOT (BATCH*SEQ)
#define NQKV (3*DIMC)

// All intermediates hold TF32 bit patterns
__device__ unsigned g_xtf [(size_t)MTOT*DIMC];               // x in tf32
__device__ unsigned g_wqkv[(size_t)DIMC*NQKV];               // W_qkv tf32
__device__ unsigned g_wprj[(size_t)DIMC*DIMC];               // W_proj tf32
__device__ unsigned g_qkv [(size_t)3*BATCH*NHEAD*SEQ*HDIM];  // [3][B][H][S][D]
__device__ unsigned g_attn[(size_t)MTOT*DIMC];               // [B*S][C] tf32

__device__ __forceinline__ unsigned f2tf(float x){
    unsigned r; asm("cvt.rna.tf32.f32 %0,%1;" : "=r"(r) : "f"(x)); return r;
}

__device__ __forceinline__ void mma8(float* c, const unsigned* a, const unsigned* b){
    asm volatile(
      "mma.sync.aligned.m16n8k8.row.col.f32.tf32.tf32.f32 "
      "{%0,%1,%2,%3},{%4,%5,%6,%7},{%8,%9},{%0,%1,%2,%3};\n"
      : "+f"(c[0]),"+f"(c[1]),"+f"(c[2]),"+f"(c[3])
      : "r"(a[0]),"r"(a[1]),"r"(a[2]),"r"(a[3]),"r"(b[0]),"r"(b[1]));
}

// ---------------------------------------------------------------------------
// Elementwise fp32 -> tf32 bit conversion
// ---------------------------------------------------------------------------
__global__ __launch_bounds__(256)
void cvt_tf32(const float4* __restrict__ src, uint4* __restrict__ dst, int n4)
{
    int i = blockIdx.x*256 + threadIdx.x;
    if(i < n4){
        float4 v = src[i];
        dst[i] = make_uint4(f2tf(v.x), f2tf(v.y), f2tf(v.z), f2tf(v.w));
    }
}

// ---------------------------------------------------------------------------
// Tensor-core GEMM: C = A[M,1024] @ B[1024,N] + bias; A,B already tf32 bits.
// 128x128x16 tiles, double-buffered (R2-proven layout, no cvt in loop).
// SCATTER=true: stores TF32 bits into g_qkv; else fp32 into out.
// ---------------------------------------------------------------------------
#define ASTR 136
#define BSTR 136

template<int N, bool SCATTER>
__global__ __launch_bounds__(256)
void gemm_mma(const unsigned* __restrict__ A, const unsigned* __restrict__ B,
              const float* __restrict__ bias, float* __restrict__ out)
{
    __shared__ __align__(16) unsigned As[2][16*ASTR];
    __shared__ __align__(16) unsigned Bs[2][16*BSTR];
    const int tid=threadIdx.x, lane=tid&31, warp=tid>>5;
    const int g=lane>>2, tg=lane&3;
    const int mbase=(warp>>2)*64, nbase=(warp&3)*32;
    const int bm=blockIdx.y*128, bn=blockIdx.x*128;
    const unsigned* Ab = (SCATTER ? A : (const unsigned*)g_attn) + (size_t)bm*DIMC;
    const unsigned* Bb = B + bn;

    uint4 ar[2], br[2];
    float acc[4][4][4];
    #pragma unroll
    for(int i=0;i<4;i++)
      #pragma unroll
      for(int j=0;j<4;j++)
        #pragma unroll
        for(int k=0;k<4;k++) acc[i][j][k]=0.f;

    const int NT = DIMC/16;

    #pragma unroll
    for(int i=0;i<2;i++){
        int idx=tid+(i<<8);
        ar[i]=*(const uint4*)(Ab + (size_t)(idx>>2)*DIMC + ((idx&3)<<2));
        br[i]=*(const uint4*)(Bb + (size_t)(idx>>5)*N + ((idx&31)<<2));
    }
    #pragma unroll
    for(int i=0;i<2;i++){
        int idx=tid+(i<<8);
        int r=idx>>2, kc=(idx&3)<<2;
        As[0][(kc+0)*ASTR+r]=ar[i].x;
        As[0][(kc+1)*ASTR+r]=ar[i].y;
        As[0][(kc+2)*ASTR+r]=ar[i].z;
        As[0][(kc+3)*ASTR+r]=ar[i].w;
        int rb=idx>>5, cb=(idx&31)<<2;
        *(uint4*)&Bs[0][rb*BSTR+cb]=br[i];
    }
    __syncthreads();

    for(int kt=0;kt<NT;kt++){
        const int buf=kt&1;
        if(kt<NT-1){
            #pragma unroll
            for(int i=0;i<2;i++){
                int idx=tid+(i<<8);
                ar[i]=*(const uint4*)(Ab + (size_t)(idx>>2)*DIMC + (kt+1)*16 + ((idx&3)<<2));
                br[i]=*(const uint4*)(Bb + (size_t)((kt+1)*16+(idx>>5))*N + ((idx&31)<<2));
            }
        }
        #pragma unroll
        for(int ks=0;ks<2;ks++){
            const int k0=ks*8;
            unsigned af[4][4], bf[4][2];
            #pragma unroll
            for(int mi=0;mi<4;mi++){
                const int m0=mbase+mi*16;
                af[mi][0]=As[buf][(k0+tg)*ASTR+m0+g];
                af[mi][1]=As[buf][(k0+tg)*ASTR+m0+g+8];
                af[mi][2]=As[buf][(k0+tg+4)*ASTR+m0+g];
                af[mi][3]=As[buf][(k0+tg+4)*ASTR+m0+g+8];
            }
            #pragma unroll
            for(int ni=0;ni<4;ni++){
                const int n0=nbase+ni*8;
                bf[ni][0]=Bs[buf][(k0+tg)*BSTR+n0+g];
                bf[ni][1]=Bs[buf][(k0+tg+4)*BSTR+n0+g];
            }
            #pragma unroll
            for(int mi=0;mi<4;mi++)
                #pragma unroll
                for(int ni=0;ni<4;ni++)
                    mma8(acc[mi][ni],af[mi],bf[ni]);
        }
        if(kt<NT-1){
            #pragma unroll
            for(int i=0;i<2;i++){
                int idx=tid+(i<<8);
                int r=idx>>2, kc=(idx&3)<<2;
                As[buf^1][(kc+0)*ASTR+r]=ar[i].x;
                As[buf^1][(kc+1)*ASTR+r]=ar[i].y;
                As[buf^1][(kc+2)*ASTR+r]=ar[i].z;
                As[buf^1][(kc+3)*ASTR+r]=ar[i].w;
                int rb=idx>>5, cb=(idx&31)<<2;
                *(uint4*)&Bs[buf^1][rb*BSTR+cb]=br[i];
            }
        }
        __syncthreads();
    }

    #pragma unroll
    for(int mi=0;mi<4;mi++){
        #pragma unroll
        for(int ni=0;ni<4;ni++){
            #pragma unroll
            for(int e=0;e<4;e++){
                const int r = bm + mbase + mi*16 + g + ((e>=2)?8:0);
                const int c = bn + nbase + ni*8 + 2*tg + (e&1);
                const float v = acc[mi][ni][e] + bias[c];
                if(SCATTER){
                    const int b=r>>11, s=r&2047;
                    const int t=c>>10, h=(c>>6)&15, d=c&63;
                    g_qkv[((((size_t)t*BATCH+b)*NHEAD+h)*SEQ+s)*HDIM+d]=f2tf(v);
                } else {
                    out[(size_t)r*N+c]=v;
                }
            }
        }
    }
}

// ---------------------------------------------------------------------------
// Flash attention: q-tile 128, 256 threads (8 warps x 16 q-rows), k-tile 64.
// All inputs tf32 bits; fills are pure uint4 copies. exp2-domain softmax.
// ---------------------------------------------------------------------------
#define QKOFF ((size_t)BATCH*NHEAD*SEQ*HDIM)
#define FSTR 68
#define FLASH_SMEM ((128*FSTR + 2*64*FSTR + 8*1024)*4)   /* 102400 B */

__global__ __launch_bounds__(256,2)
void flash_mma()
{
    extern __shared__ __align__(16) unsigned sm[];
    unsigned* Qs=sm;                  // 128 x FSTR
    unsigned* Ks=Qs+128*FSTR;         // 64 x FSTR
    unsigned* Vs=Ks+64*FSTR;          // 64 x FSTR
    unsigned* Ps=Vs+64*FSTR;          // 8 x 1024
    const int tid=threadIdx.x, lane=tid&31, warp=tid>>5;
    const int g=lane>>2, tg=lane&3;
    const int qb=warp*16;
    const int b=blockIdx.y>>4, h=blockIdx.y&15;
    const int q0=blockIdx.x*128;
    const unsigned* Qg=g_qkv + ((size_t)(b*NHEAD+h))*SEQ*HDIM;
    const unsigned* Kg=Qg + QKOFF;
    const unsigned* Vg=Kg + QKOFF;
    unsigned* Pw = Ps + warp*1024;

    #pragma unroll
    for(int i=0;i<8;i++){
        int idx=tid+(i<<8);
        int r=idx>>4, c=(idx&15)<<2;
        *(uint4*)&Qs[r*FSTR+c] = *(const uint4*)(Qg+(size_t)(q0+r)*HDIM+c);
    }

    float oc[8][4];
    #pragma unroll
    for(int i=0;i<8;i++)
        #pragma unroll
        for(int j=0;j<4;j++) oc[i][j]=0.f;
    float m0=-1e30f, m1=-1e30f, l0=0.f, l1=0.f;
    const float scale=0.125f*1.44269504089f;   // fold log2e: exp2 domain

    for(int kt=0;kt<SEQ/64;kt++){
        __syncthreads();
        #pragma unroll
        for(int i=0;i<4;i++){
            int idx=tid+(i<<8);
            int r=idx>>4, c=(idx&15)<<2;
            *(uint4*)&Ks[r*FSTR+c] = *(const uint4*)(Kg+(size_t)(kt*64+r)*HDIM+c);
            *(uint4*)&Vs[r*FSTR+c] = *(const uint4*)(Vg+(size_t)(kt*64+r)*HDIM+c);
        }
        __syncthreads();

        // S = Q @ K^T
        float sc[8][4];
        #pragma unroll
        for(int i=0;i<8;i++)
            #pragma unroll
            for(int j=0;j<4;j++) sc[i][j]=0.f;
        #pragma unroll
        for(int ks=0;ks<8;ks++){
            const int k0=ks*8;
            unsigned af[4];
            af[0]=Qs[(qb+g  )*FSTR+k0+tg];
            af[1]=Qs[(qb+g+8)*FSTR+k0+tg];
            af[2]=Qs[(qb+g  )*FSTR+k0+tg+4];
            af[3]=Qs[(qb+g+8)*FSTR+k0+tg+4];
            #pragma unroll
            for(int ni=0;ni<8;ni++){
                unsigned bf[2];
                bf[0]=Ks[(ni*8+g)*FSTR+k0+tg];
                bf[1]=Ks[(ni*8+g)*FSTR+k0+tg+4];
                mma8(sc[ni],af,bf);
            }
        }

        // online softmax (exp2 domain)
        float mx0=-1e30f, mx1=-1e30f;
        #pragma unroll
        for(int ni=0;ni<8;ni++){
            sc[ni][0]*=scale; sc[ni][1]*=scale; sc[ni][2]*=scale; sc[ni][3]*=scale;
            mx0=fmaxf(mx0,fmaxf(sc[ni][0],sc[ni][1]));
            mx1=fmaxf(mx1,fmaxf(sc[ni][2],sc[ni][3]));
        }
        mx0=fmaxf(mx0,__shfl_xor_sync(0xffffffffu,mx0,1));
        mx0=fmaxf(mx0,__shfl_xor_sync(0xffffffffu,mx0,2));
        mx1=fmaxf(mx1,__shfl_xor_sync(0xffffffffu,mx1,1));
        mx1=fmaxf(mx1,__shfl_xor_sync(0xffffffffu,mx1,2));
        const float nm0=fmaxf(m0,mx0), nm1=fmaxf(m1,mx1);
        const float a0=exp2f(m0-nm0), a1=exp2f(m1-nm1);
        m0=nm0; m1=nm1;
        float s0=0.f, s1=0.f;
        #pragma unroll
        for(int ni=0;ni<8;ni++){
            sc[ni][0]=exp2f(sc[ni][0]-nm0); sc[ni][1]=exp2f(sc[ni][1]-nm0);
            sc[ni][2]=exp2f(sc[ni][2]-nm1); sc[ni][3]=exp2f(sc[ni][3]-nm1);
            s0+=sc[ni][0]+sc[ni][1];
            s1+=sc[ni][2]+sc[ni][3];
        }
        s0+=__shfl_xor_sync(0xffffffffu,s0,1); s0+=__shfl_xor_sync(0xffffffffu,s0,2);
        s1+=__shfl_xor_sync(0xffffffffu,s1,1); s1+=__shfl_xor_sync(0xffffffffu,s1,2);
        l0=l0*a0+s0; l1=l1*a1+s1;

        // P -> per-warp fragment buffer
        #pragma unroll
        for(int ni=0;ni<8;ni++){
            unsigned* pp=&Pw[(ni*32 + g*4 + ((2*tg)&3))*4 + 2*(tg>>1)];
            *(uint2*)pp    =make_uint2(f2tf(sc[ni][0]), f2tf(sc[ni][2]));
            *(uint2*)(pp+4)=make_uint2(f2tf(sc[ni][1]), f2tf(sc[ni][3]));
        }
        __syncwarp();

        #pragma unroll
        for(int di=0;di<8;di++){
            oc[di][0]*=a0; oc[di][1]*=a0; oc[di][2]*=a1; oc[di][3]*=a1;
        }
        // O += P @ V
        #pragma unroll
        for(int ks=0;ks<8;ks++){
            uint4 af4=*(const uint4*)&Pw[ks*128 + lane*4];
            const unsigned* AF=(const unsigned*)&af4;
            const int k0=ks*8;
            #pragma unroll
            for(int di=0;di<8;di++){
                unsigned bf[2];
                bf[0]=Vs[(k0+tg  )*FSTR+di*8+g];
                bf[1]=Vs[(k0+tg+4)*FSTR+di*8+g];
                mma8(oc[di],AF,bf);
            }
        }
        __syncwarp();
    }

    const float i0=1.f/l0, i1=1.f/l1;
    const int r0=q0+qb+g, r1=r0+8;
    unsigned* O0=&g_attn[((size_t)(b*SEQ)+r0)*DIMC + h*HDIM];
    unsigned* O1=&g_attn[((size_t)(b*SEQ)+r1)*DIMC + h*HDIM];
    #pragma unroll
    for(int di=0;di<8;di++){
        const int c=di*8+2*tg;
        *(uint2*)&O0[c]=make_uint2(f2tf(oc[di][0]*i0), f2tf(oc[di][1]*i0));
        *(uint2*)&O1[c]=make_uint2(f2tf(oc[di][2]*i1), f2tf(oc[di][3]*i1));
    }
}

// ---------------------------------------------------------------------------
extern "C" void kernel_launch(void* const* d_in, const int* in_sizes, int n_in,
                              void* d_out, int out_size)
{
    const float* x     = (const float*)d_in[0];
    const float* Wqkv  = (const float*)d_in[1];
    const float* bqkv  = (const float*)d_in[2];
    const float* Wproj = (const float*)d_in[3];
    const float* bproj = (const float*)d_in[4];
    float* out = (float*)d_out;

    cudaFuncSetAttribute(flash_mma, cudaFuncAttributeMaxDynamicSharedMemorySize, FLASH_SMEM);

    unsigned *xtf, *wqkv, *wprj;
    cudaGetSymbolAddress((void**)&xtf,  g_xtf);
    cudaGetSymbolAddress((void**)&wqkv, g_wqkv);
    cudaGetSymbolAddress((void**)&wprj, g_wprj);

    cvt_tf32<<<(MTOT*DIMC/4+255)/256, 256>>>((const float4*)x,     (uint4*)xtf,  MTOT*DIMC/4);
    cvt_tf32<<<(DIMC*NQKV/4+255)/256, 256>>>((const float4*)Wqkv,  (uint4*)wqkv, DIMC*NQKV/4);
    cvt_tf32<<<(DIMC*DIMC/4+255)/256, 256>>>((const float4*)Wproj, (uint4*)wprj, DIMC*DIMC/4);

    dim3 g1(NQKV/128, MTOT/128);   // (24, 64)
    gemm_mma<NQKV, true><<<g1, 256>>>(xtf, wqkv, bqkv, nullptr);

    dim3 g2(SEQ/128, BATCH*NHEAD); // (16, 64)
    flash_mma<<<g2, 256, FLASH_SMEM>>>();

    dim3 g3(DIMC/128, MTOT/128);   // (8, 64)
    gemm_mma<DIMC, false><<<g3, 256>>>(nullptr, wprj, bproj, out);
}

// round 9
// speedup vs baseline: 1.5629x; 1.0168x over previous
#include <cuda_runtime.h>

#define DIMC 1024
#define NHEAD 16
#define HDIM 64
#define BATCH 4
#define SEQ 2048
#define MTOT (BATCH*SEQ)
#define NQKV (3*DIMC)

// All intermediates hold TF32 bit patterns
__device__ unsigned g_xtf [(size_t)MTOT*DIMC];
__device__ unsigned g_wqkv[(size_t)DIMC*NQKV];
__device__ unsigned g_wprj[(size_t)DIMC*DIMC];
__device__ unsigned g_qkv [(size_t)3*BATCH*NHEAD*SEQ*HDIM];  // [3][B][H][S][D]
__device__ unsigned g_attn[(size_t)MTOT*DIMC];               // [B*S][C] tf32

__device__ __forceinline__ unsigned f2tf(float x){
    unsigned r; asm("cvt.rna.tf32.f32 %0,%1;" : "=r"(r) : "f"(x)); return r;
}

__device__ __forceinline__ void mma8(float* c, const unsigned* a, const unsigned* b){
    asm volatile(
      "mma.sync.aligned.m16n8k8.row.col.f32.tf32.tf32.f32 "
      "{%0,%1,%2,%3},{%4,%5,%6,%7},{%8,%9},{%0,%1,%2,%3};\n"
      : "+f"(c[0]),"+f"(c[1]),"+f"(c[2]),"+f"(c[3])
      : "r"(a[0]),"r"(a[1]),"r"(a[2]),"r"(a[3]),"r"(b[0]),"r"(b[1]));
}

__global__ __launch_bounds__(256)
void cvt_tf32(const float4* __restrict__ src, uint4* __restrict__ dst, int n4)
{
    int i = blockIdx.x*256 + threadIdx.x;
    if(i < n4){
        float4 v = src[i];
        dst[i] = make_uint4(f2tf(v.x), f2tf(v.y), f2tf(v.z), f2tf(v.w));
    }
}

// ---------------------------------------------------------------------------
// Tensor-core GEMM, 64x64 warp tiles: C = A[M,1024]@B[1024,N] + bias.
// 128 threads (4 warps) per 128x128x16 tile, double-buffered tf32 smem.
// Warp w: rows (w&1)*64, cols (w>>1)*64. 32 MMAs per warp per ks.
// Layouts identical to proven R8: As [k][m] str 136, Bs [k][n] str 136.
// ---------------------------------------------------------------------------
#define ASTR 136
#define BSTR 136

template<int N, bool SCATTER>
__global__ __launch_bounds__(128)
void gemm_mma(const unsigned* __restrict__ A, const unsigned* __restrict__ B,
              const float* __restrict__ bias, float* __restrict__ out)
{
    __shared__ __align__(16) unsigned As[2][16*ASTR];
    __shared__ __align__(16) unsigned Bs[2][16*BSTR];
    const int tid=threadIdx.x, lane=tid&31, warp=tid>>5;
    const int g=lane>>2, tg=lane&3;
    const int mbase=(warp&1)*64, nbase=(warp>>1)*64;
    const int bm=blockIdx.y*128, bn=blockIdx.x*128;
    const unsigned* Ab = (SCATTER ? A : (const unsigned*)g_attn) + (size_t)bm*DIMC;
    const unsigned* Bb = B + bn;

    uint4 ar[4], br[4];
    float acc[4][8][4];
    #pragma unroll
    for(int i=0;i<4;i++)
      #pragma unroll
      for(int j=0;j<8;j++)
        #pragma unroll
        for(int k=0;k<4;k++) acc[i][j][k]=0.f;

    const int NT = DIMC/16;

    #pragma unroll
    for(int i=0;i<4;i++){
        int idx=tid+(i<<7);
        ar[i]=*(const uint4*)(Ab + (size_t)(idx>>2)*DIMC + ((idx&3)<<2));
        br[i]=*(const uint4*)(Bb + (size_t)(idx>>5)*N + ((idx&31)<<2));
    }
    #pragma unroll
    for(int i=0;i<4;i++){
        int idx=tid+(i<<7);
        int r=idx>>2, kc=(idx&3)<<2;
        As[0][(kc+0)*ASTR+r]=ar[i].x;
        As[0][(kc+1)*ASTR+r]=ar[i].y;
        As[0][(kc+2)*ASTR+r]=ar[i].z;
        As[0][(kc+3)*ASTR+r]=ar[i].w;
        int rb=idx>>5, cb=(idx&31)<<2;
        *(uint4*)&Bs[0][rb*BSTR+cb]=br[i];
    }
    __syncthreads();

    for(int kt=0;kt<NT;kt++){
        const int buf=kt&1;
        if(kt<NT-1){
            #pragma unroll
            for(int i=0;i<4;i++){
                int idx=tid+(i<<7);
                ar[i]=*(const uint4*)(Ab + (size_t)(idx>>2)*DIMC + (kt+1)*16 + ((idx&3)<<2));
                br[i]=*(const uint4*)(Bb + (size_t)((kt+1)*16+(idx>>5))*N + ((idx&31)<<2));
            }
        }
        #pragma unroll
        for(int ks=0;ks<2;ks++){
            const int k0=ks*8;
            unsigned af[4][4], bf[8][2];
            #pragma unroll
            for(int mi=0;mi<4;mi++){
                const int m0=mbase+mi*16;
                af[mi][0]=As[buf][(k0+tg)*ASTR+m0+g];
                af[mi][1]=As[buf][(k0+tg)*ASTR+m0+g+8];
                af[mi][2]=As[buf][(k0+tg+4)*ASTR+m0+g];
                af[mi][3]=As[buf][(k0+tg+4)*ASTR+m0+g+8];
            }
            #pragma unroll
            for(int ni=0;ni<8;ni++){
                const int n0=nbase+ni*8;
                bf[ni][0]=Bs[buf][(k0+tg)*BSTR+n0+g];
                bf[ni][1]=Bs[buf][(k0+tg+4)*BSTR+n0+g];
            }
            #pragma unroll
            for(int mi=0;mi<4;mi++)
                #pragma unroll
                for(int ni=0;ni<8;ni++)
                    mma8(acc[mi][ni],af[mi],bf[ni]);
        }
        if(kt<NT-1){
            #pragma unroll
            for(int i=0;i<4;i++){
                int idx=tid+(i<<7);
                int r=idx>>2, kc=(idx&3)<<2;
                As[buf^1][(kc+0)*ASTR+r]=ar[i].x;
                As[buf^1][(kc+1)*ASTR+r]=ar[i].y;
                As[buf^1][(kc+2)*ASTR+r]=ar[i].z;
                As[buf^1][(kc+3)*ASTR+r]=ar[i].w;
                int rb=idx>>5, cb=(idx&31)<<2;
                *(uint4*)&Bs[buf^1][rb*BSTR+cb]=br[i];
            }
        }
        __syncthreads();
    }

    #pragma unroll
    for(int mi=0;mi<4;mi++){
        #pragma unroll
        for(int ni=0;ni<8;ni++){
            #pragma unroll
            for(int e=0;e<4;e++){
                const int r = bm + mbase + mi*16 + g + ((e>=2)?8:0);
                const int c = bn + nbase + ni*8 + 2*tg + (e&1);
                const float v = acc[mi][ni][e] + bias[c];
                if(SCATTER){
                    const int b=r>>11, s=r&2047;
                    const int t=c>>10, h=(c>>6)&15, d=c&63;
                    g_qkv[((((size_t)t*BATCH+b)*NHEAD+h)*SEQ+s)*HDIM+d]=f2tf(v);
                } else {
                    out[(size_t)r*N+c]=v;
                }
            }
        }
    }
}

// ---------------------------------------------------------------------------
// Flash attention (R8 version, unchanged): q-tile 128, 256 thr, k-tile 64.
// ---------------------------------------------------------------------------
#define QKOFF ((size_t)BATCH*NHEAD*SEQ*HDIM)
#define FSTR 68
#define FLASH_SMEM ((128*FSTR + 2*64*FSTR + 8*1024)*4)   /* 102400 B */

__global__ __launch_bounds__(256,2)
void flash_mma()
{
    extern __shared__ __align__(16) unsigned sm[];
    unsigned* Qs=sm;
    unsigned* Ks=Qs+128*FSTR;
    unsigned* Vs=Ks+64*FSTR;
    unsigned* Ps=Vs+64*FSTR;
    const int tid=threadIdx.x, lane=tid&31, warp=tid>>5;
    const int g=lane>>2, tg=lane&3;
    const int qb=warp*16;
    const int b=blockIdx.y>>4, h=blockIdx.y&15;
    const int q0=blockIdx.x*128;
    const unsigned* Qg=g_qkv + ((size_t)(b*NHEAD+h))*SEQ*HDIM;
    const unsigned* Kg=Qg + QKOFF;
    const unsigned* Vg=Kg + QKOFF;
    unsigned* Pw = Ps + warp*1024;

    #pragma unroll
    for(int i=0;i<8;i++){
        int idx=tid+(i<<8);
        int r=idx>>4, c=(idx&15)<<2;
        *(uint4*)&Qs[r*FSTR+c] = *(const uint4*)(Qg+(size_t)(q0+r)*HDIM+c);
    }

    float oc[8][4];
    #pragma unroll
    for(int i=0;i<8;i++)
        #pragma unroll
        for(int j=0;j<4;j++) oc[i][j]=0.f;
    float m0=-1e30f, m1=-1e30f, l0=0.f, l1=0.f;
    const float scale=0.125f*1.44269504089f;

    for(int kt=0;kt<SEQ/64;kt++){
        __syncthreads();
        #pragma unroll
        for(int i=0;i<4;i++){
            int idx=tid+(i<<8);
            int r=idx>>4, c=(idx&15)<<2;
            *(uint4*)&Ks[r*FSTR+c] = *(const uint4*)(Kg+(size_t)(kt*64+r)*HDIM+c);
            *(uint4*)&Vs[r*FSTR+c] = *(const uint4*)(Vg+(size_t)(kt*64+r)*HDIM+c);
        }
        __syncthreads();

        float sc[8][4];
        #pragma unroll
        for(int i=0;i<8;i++)
            #pragma unroll
            for(int j=0;j<4;j++) sc[i][j]=0.f;
        #pragma unroll
        for(int ks=0;ks<8;ks++){
            const int k0=ks*8;
            unsigned af[4];
            af[0]=Qs[(qb+g  )*FSTR+k0+tg];
            af[1]=Qs[(qb+g+8)*FSTR+k0+tg];
            af[2]=Qs[(qb+g  )*FSTR+k0+tg+4];
            af[3]=Qs[(qb+g+8)*FSTR+k0+tg+4];
            #pragma unroll
            for(int ni=0;ni<8;ni++){
                unsigned bf[2];
                bf[0]=Ks[(ni*8+g)*FSTR+k0+tg];
                bf[1]=Ks[(ni*8+g)*FSTR+k0+tg+4];
                mma8(sc[ni],af,bf);
            }
        }

        float mx0=-1e30f, mx1=-1e30f;
        #pragma unroll
        for(int ni=0;ni<8;ni++){
            sc[ni][0]*=scale; sc[ni][1]*=scale; sc[ni][2]*=scale; sc[ni][3]*=scale;
            mx0=fmaxf(mx0,fmaxf(sc[ni][0],sc[ni][1]));
            mx1=fmaxf(mx1,fmaxf(sc[ni][2],sc[ni][3]));
        }
        mx0=fmaxf(mx0,__shfl_xor_sync(0xffffffffu,mx0,1));
        mx0=fmaxf(mx0,__shfl_xor_sync(0xffffffffu,mx0,2));
        mx1=fmaxf(mx1,__shfl_xor_sync(0xffffffffu,mx1,1));
        mx1=fmaxf(mx1,__shfl_xor_sync(0xffffffffu,mx1,2));
        const float nm0=fmaxf(m0,mx0), nm1=fmaxf(m1,mx1);
        const float a0=exp2f(m0-nm0), a1=exp2f(m1-nm1);
        m0=nm0; m1=nm1;
        float s0=0.f, s1=0.f;
        #pragma unroll
        for(int ni=0;ni<8;ni++){
            sc[ni][0]=exp2f(sc[ni][0]-nm0); sc[ni][1]=exp2f(sc[ni][1]-nm0);
            sc[ni][2]=exp2f(sc[ni][2]-nm1); sc[ni][3]=exp2f(sc[ni][3]-nm1);
            s0+=sc[ni][0]+sc[ni][1];
            s1+=sc[ni][2]+sc[ni][3];
        }
        s0+=__shfl_xor_sync(0xffffffffu,s0,1); s0+=__shfl_xor_sync(0xffffffffu,s0,2);
        s1+=__shfl_xor_sync(0xffffffffu,s1,1); s1+=__shfl_xor_sync(0xffffffffu,s1,2);
        l0=l0*a0+s0; l1=l1*a1+s1;

        #pragma unroll
        for(int ni=0;ni<8;ni++){
            unsigned* pp=&Pw[(ni*32 + g*4 + ((2*tg)&3))*4 + 2*(tg>>1)];
            *(uint2*)pp    =make_uint2(f2tf(sc[ni][0]), f2tf(sc[ni][2]));
            *(uint2*)(pp+4)=make_uint2(f2tf(sc[ni][1]), f2tf(sc[ni][3]));
        }
        __syncwarp();

        #pragma unroll
        for(int di=0;di<8;di++){
            oc[di][0]*=a0; oc[di][1]*=a0; oc[di][2]*=a1; oc[di][3]*=a1;
        }
        #pragma unroll
        for(int ks=0;ks<8;ks++){
            uint4 af4=*(const uint4*)&Pw[ks*128 + lane*4];
            const unsigned* AF=(const unsigned*)&af4;
            const int k0=ks*8;
            #pragma unroll
            for(int di=0;di<8;di++){
                unsigned bf[2];
                bf[0]=Vs[(k0+tg  )*FSTR+di*8+g];
                bf[1]=Vs[(k0+tg+4)*FSTR+di*8+g];
                mma8(oc[di],AF,bf);
            }
        }
        __syncwarp();
    }

    const float i0=1.f/l0, i1=1.f/l1;
    const int r0=q0+qb+g, r1=r0+8;
    unsigned* O0=&g_attn[((size_t)(b*SEQ)+r0)*DIMC + h*HDIM];
    unsigned* O1=&g_attn[((size_t)(b*SEQ)+r1)*DIMC + h*HDIM];
    #pragma unroll
    for(int di=0;di<8;di++){
        const int c=di*8+2*tg;
        *(uint2*)&O0[c]=make_uint2(f2tf(oc[di][0]*i0), f2tf(oc[di][1]*i0));
        *(uint2*)&O1[c]=make_uint2(f2tf(oc[di][2]*i1), f2tf(oc[di][3]*i1));
    }
}

// ---------------------------------------------------------------------------
extern "C" void kernel_launch(void* const* d_in, const int* in_sizes, int n_in,
                              void* d_out, int out_size)
{
    const float* x     = (const float*)d_in[0];
    const float* Wqkv  = (const float*)d_in[1];
    const float* bqkv  = (const float*)d_in[2];
    const float* Wproj = (const float*)d_in[3];
    const float* bproj = (const float*)d_in[4];
    float* out = (float*)d_out;

    cudaFuncSetAttribute(flash_mma, cudaFuncAttributeMaxDynamicSharedMemorySize, FLASH_SMEM);

    unsigned *xtf, *wqkv, *wprj;
    cudaGetSymbolAddress((void**)&xtf,  g_xtf);
    cudaGetSymbolAddress((void**)&wqkv, g_wqkv);
    cudaGetSymbolAddress((void**)&wprj, g_wprj);

    cvt_tf32<<<(MTOT*DIMC/4+255)/256, 256>>>((const float4*)x,     (uint4*)xtf,  MTOT*DIMC/4);
    cvt_tf32<<<(DIMC*NQKV/4+255)/256, 256>>>((const float4*)Wqkv,  (uint4*)wqkv, DIMC*NQKV/4);
    cvt_tf32<<<(DIMC*DIMC/4+255)/256, 256>>>((const float4*)Wproj, (uint4*)wprj, DIMC*DIMC/4);

    dim3 g1(NQKV/128, MTOT/128);   // (24, 64)
    gemm_mma<NQKV, true><<<g1, 128>>>(xtf, wqkv, bqkv, nullptr);

    dim3 g2(SEQ/128, BATCH*NHEAD); // (16, 64)
    flash_mma<<<g2, 256, FLASH_SMEM>>>();

    dim3 g3(DIMC/128, MTOT/128);   // (8, 64)
    gemm_mma<DIMC, false><<<g3, 128>>>(nullptr, wprj, bproj, out);
}

// round 10
// speedup vs baseline: 1.7521x; 1.1210x over previous
#include <cuda_runtime.h>

#define DIMC 1024
#define NHEAD 16
#define HDIM 64
#define BATCH 4
#define SEQ 2048
#define MTOT (BATCH*SEQ)
#define NQKV (3*DIMC)

// All intermediates hold TF32 bit patterns
__device__ unsigned g_xtf [(size_t)MTOT*DIMC];
__device__ unsigned g_wqkv[(size_t)DIMC*NQKV];
__device__ unsigned g_wprj[(size_t)DIMC*DIMC];
__device__ unsigned g_qkv [(size_t)3*BATCH*NHEAD*SEQ*HDIM];  // [3][B][H][S][D]
__device__ unsigned g_attn[(size_t)MTOT*DIMC];               // [B*S][C] tf32

__device__ __forceinline__ unsigned f2tf(float x){
    unsigned r; asm("cvt.rna.tf32.f32 %0,%1;" : "=r"(r) : "f"(x)); return r;
}

__device__ __forceinline__ void mma8(float* c, const unsigned* a, const unsigned* b){
    asm volatile(
      "mma.sync.aligned.m16n8k8.row.col.f32.tf32.tf32.f32 "
      "{%0,%1,%2,%3},{%4,%5,%6,%7},{%8,%9},{%0,%1,%2,%3};\n"
      : "+f"(c[0]),"+f"(c[1]),"+f"(c[2]),"+f"(c[3])
      : "r"(a[0]),"r"(a[1]),"r"(a[2]),"r"(a[3]),"r"(b[0]),"r"(b[1]));
}

__global__ __launch_bounds__(256)
void cvt_tf32(const float4* __restrict__ src, uint4* __restrict__ dst, int n4)
{
    int i = blockIdx.x*256 + threadIdx.x;
    if(i < n4){
        float4 v = src[i];
        dst[i] = make_uint4(f2tf(v.x), f2tf(v.y), f2tf(v.z), f2tf(v.w));
    }
}

// ---------------------------------------------------------------------------
// Tensor-core GEMM (R9 version): 64x64 warp tiles, 128 threads, 128x128x16.
// ---------------------------------------------------------------------------
#define ASTR 136
#define BSTR 136

template<int N, bool SCATTER>
__global__ __launch_bounds__(128)
void gemm_mma(const unsigned* __restrict__ A, const unsigned* __restrict__ B,
              const float* __restrict__ bias, float* __restrict__ out)
{
    __shared__ __align__(16) unsigned As[2][16*ASTR];
    __shared__ __align__(16) unsigned Bs[2][16*BSTR];
    const int tid=threadIdx.x, lane=tid&31, warp=tid>>5;
    const int g=lane>>2, tg=lane&3;
    const int mbase=(warp&1)*64, nbase=(warp>>1)*64;
    const int bm=blockIdx.y*128, bn=blockIdx.x*128;
    const unsigned* Ab = (SCATTER ? A : (const unsigned*)g_attn) + (size_t)bm*DIMC;
    const unsigned* Bb = B + bn;

    uint4 ar[4], br[4];
    float acc[4][8][4];
    #pragma unroll
    for(int i=0;i<4;i++)
      #pragma unroll
      for(int j=0;j<8;j++)
        #pragma unroll
        for(int k=0;k<4;k++) acc[i][j][k]=0.f;

    const int NT = DIMC/16;

    #pragma unroll
    for(int i=0;i<4;i++){
        int idx=tid+(i<<7);
        ar[i]=*(const uint4*)(Ab + (size_t)(idx>>2)*DIMC + ((idx&3)<<2));
        br[i]=*(const uint4*)(Bb + (size_t)(idx>>5)*N + ((idx&31)<<2));
    }
    #pragma unroll
    for(int i=0;i<4;i++){
        int idx=tid+(i<<7);
        int r=idx>>2, kc=(idx&3)<<2;
        As[0][(kc+0)*ASTR+r]=ar[i].x;
        As[0][(kc+1)*ASTR+r]=ar[i].y;
        As[0][(kc+2)*ASTR+r]=ar[i].z;
        As[0][(kc+3)*ASTR+r]=ar[i].w;
        int rb=idx>>5, cb=(idx&31)<<2;
        *(uint4*)&Bs[0][rb*BSTR+cb]=br[i];
    }
    __syncthreads();

    for(int kt=0;kt<NT;kt++){
        const int buf=kt&1;
        if(kt<NT-1){
            #pragma unroll
            for(int i=0;i<4;i++){
                int idx=tid+(i<<7);
                ar[i]=*(const uint4*)(Ab + (size_t)(idx>>2)*DIMC + (kt+1)*16 + ((idx&3)<<2));
                br[i]=*(const uint4*)(Bb + (size_t)((kt+1)*16+(idx>>5))*N + ((idx&31)<<2));
            }
        }
        #pragma unroll
        for(int ks=0;ks<2;ks++){
            const int k0=ks*8;
            unsigned af[4][4], bf[8][2];
            #pragma unroll
            for(int mi=0;mi<4;mi++){
                const int m0=mbase+mi*16;
                af[mi][0]=As[buf][(k0+tg)*ASTR+m0+g];
                af[mi][1]=As[buf][(k0+tg)*ASTR+m0+g+8];
                af[mi][2]=As[buf][(k0+tg+4)*ASTR+m0+g];
                af[mi][3]=As[buf][(k0+tg+4)*ASTR+m0+g+8];
            }
            #pragma unroll
            for(int ni=0;ni<8;ni++){
                const int n0=nbase+ni*8;
                bf[ni][0]=Bs[buf][(k0+tg)*BSTR+n0+g];
                bf[ni][1]=Bs[buf][(k0+tg+4)*BSTR+n0+g];
            }
            #pragma unroll
            for(int mi=0;mi<4;mi++)
                #pragma unroll
                for(int ni=0;ni<8;ni++)
                    mma8(acc[mi][ni],af[mi],bf[ni]);
        }
        if(kt<NT-1){
            #pragma unroll
            for(int i=0;i<4;i++){
                int idx=tid+(i<<7);
                int r=idx>>2, kc=(idx&3)<<2;
                As[buf^1][(kc+0)*ASTR+r]=ar[i].x;
                As[buf^1][(kc+1)*ASTR+r]=ar[i].y;
                As[buf^1][(kc+2)*ASTR+r]=ar[i].z;
                As[buf^1][(kc+3)*ASTR+r]=ar[i].w;
                int rb=idx>>5, cb=(idx&31)<<2;
                *(uint4*)&Bs[buf^1][rb*BSTR+cb]=br[i];
            }
        }
        __syncthreads();
    }

    #pragma unroll
    for(int mi=0;mi<4;mi++){
        #pragma unroll
        for(int ni=0;ni<8;ni++){
            #pragma unroll
            for(int e=0;e<4;e++){
                const int r = bm + mbase + mi*16 + g + ((e>=2)?8:0);
                const int c = bn + nbase + ni*8 + 2*tg + (e&1);
                const float v = acc[mi][ni][e] + bias[c];
                if(SCATTER){
                    const int b=r>>11, s=r&2047;
                    const int t=c>>10, h=(c>>6)&15, d=c&63;
                    g_qkv[((((size_t)t*BATCH+b)*NHEAD+h)*SEQ+s)*HDIM+d]=f2tf(v);
                } else {
                    out[(size_t)r*N+c]=v;
                }
            }
        }
    }
}

// ---------------------------------------------------------------------------
// Flash attention: 128 threads, 4 warps x 32 q-rows (2 m-tiles), q-tile 128,
// k-tile 64. Doubles K/V fragment reuse vs R8 (1.5 wf/MMA from 2.5).
// ---------------------------------------------------------------------------
#define QKOFF ((size_t)BATCH*NHEAD*SEQ*HDIM)
#define FSTR 68
#define FLASH_SMEM ((128*FSTR + 2*64*FSTR + 4*2048)*4)   /* 102400 B */

__global__ __launch_bounds__(128)
void flash_mma()
{
    extern __shared__ __align__(16) unsigned sm[];
    unsigned* Qs=sm;                  // 128 x FSTR
    unsigned* Ks=Qs+128*FSTR;         // 64 x FSTR
    unsigned* Vs=Ks+64*FSTR;          // 64 x FSTR
    unsigned* Ps=Vs+64*FSTR;          // 4 warps x 2048 words
    const int tid=threadIdx.x, lane=tid&31, warp=tid>>5;
    const int g=lane>>2, tg=lane&3;
    const int qb=warp*32;
    const int b=blockIdx.y>>4, h=blockIdx.y&15;
    const int q0=blockIdx.x*128;
    const unsigned* Qg=g_qkv + ((size_t)(b*NHEAD+h))*SEQ*HDIM;
    const unsigned* Kg=Qg + QKOFF;
    const unsigned* Vg=Kg + QKOFF;
    unsigned* Pw = Ps + warp*2048;    // per-warp: 2 m-tiles x 1024 words

    #pragma unroll
    for(int i=0;i<16;i++){
        int idx=tid+(i<<7);
        int r=idx>>4, c=(idx&15)<<2;
        *(uint4*)&Qs[r*FSTR+c] = *(const uint4*)(Qg+(size_t)(q0+r)*HDIM+c);
    }

    float oc[2][8][4];
    #pragma unroll
    for(int mi=0;mi<2;mi++)
        #pragma unroll
        for(int i=0;i<8;i++)
            #pragma unroll
            for(int j=0;j<4;j++) oc[mi][i][j]=0.f;
    float mrow[4], lrow[4];
    #pragma unroll
    for(int i=0;i<4;i++){ mrow[i]=-1e30f; lrow[i]=0.f; }
    const float scale=0.125f*1.44269504089f;

    for(int kt=0;kt<SEQ/64;kt++){
        __syncthreads();
        #pragma unroll
        for(int i=0;i<8;i++){
            int idx=tid+(i<<7);
            int r=idx>>4, c=(idx&15)<<2;
            *(uint4*)&Ks[r*FSTR+c] = *(const uint4*)(Kg+(size_t)(kt*64+r)*HDIM+c);
            *(uint4*)&Vs[r*FSTR+c] = *(const uint4*)(Vg+(size_t)(kt*64+r)*HDIM+c);
        }
        __syncthreads();

        // S = Q @ K^T : 2 m-tiles x 8 key-tiles
        float sc[2][8][4];
        #pragma unroll
        for(int mi=0;mi<2;mi++)
            #pragma unroll
            for(int i=0;i<8;i++)
                #pragma unroll
                for(int j=0;j<4;j++) sc[mi][i][j]=0.f;
        #pragma unroll
        for(int ks=0;ks<8;ks++){
            const int k0=ks*8;
            unsigned af[2][4];
            #pragma unroll
            for(int mi=0;mi<2;mi++){
                const int m0=qb+mi*16;
                af[mi][0]=Qs[(m0+g  )*FSTR+k0+tg];
                af[mi][1]=Qs[(m0+g+8)*FSTR+k0+tg];
                af[mi][2]=Qs[(m0+g  )*FSTR+k0+tg+4];
                af[mi][3]=Qs[(m0+g+8)*FSTR+k0+tg+4];
            }
            #pragma unroll
            for(int ni=0;ni<8;ni++){
                unsigned bf[2];
                bf[0]=Ks[(ni*8+g)*FSTR+k0+tg];
                bf[1]=Ks[(ni*8+g)*FSTR+k0+tg+4];
                mma8(sc[0][ni],af[0],bf);
                mma8(sc[1][ni],af[1],bf);
            }
        }

        // online softmax per m-tile
        float al[4];
        #pragma unroll
        for(int mi=0;mi<2;mi++){
            float mx0=-1e30f, mx1=-1e30f;
            #pragma unroll
            for(int ni=0;ni<8;ni++){
                sc[mi][ni][0]*=scale; sc[mi][ni][1]*=scale;
                sc[mi][ni][2]*=scale; sc[mi][ni][3]*=scale;
                mx0=fmaxf(mx0,fmaxf(sc[mi][ni][0],sc[mi][ni][1]));
                mx1=fmaxf(mx1,fmaxf(sc[mi][ni][2],sc[mi][ni][3]));
            }
            mx0=fmaxf(mx0,__shfl_xor_sync(0xffffffffu,mx0,1));
            mx0=fmaxf(mx0,__shfl_xor_sync(0xffffffffu,mx0,2));
            mx1=fmaxf(mx1,__shfl_xor_sync(0xffffffffu,mx1,1));
            mx1=fmaxf(mx1,__shfl_xor_sync(0xffffffffu,mx1,2));
            const float nm0=fmaxf(mrow[mi*2],mx0), nm1=fmaxf(mrow[mi*2+1],mx1);
            al[mi*2]  =exp2f(mrow[mi*2]-nm0);
            al[mi*2+1]=exp2f(mrow[mi*2+1]-nm1);
            mrow[mi*2]=nm0; mrow[mi*2+1]=nm1;
            float s0=0.f, s1=0.f;
            #pragma unroll
            for(int ni=0;ni<8;ni++){
                sc[mi][ni][0]=exp2f(sc[mi][ni][0]-nm0);
                sc[mi][ni][1]=exp2f(sc[mi][ni][1]-nm0);
                sc[mi][ni][2]=exp2f(sc[mi][ni][2]-nm1);
                sc[mi][ni][3]=exp2f(sc[mi][ni][3]-nm1);
                s0+=sc[mi][ni][0]+sc[mi][ni][1];
                s1+=sc[mi][ni][2]+sc[mi][ni][3];
            }
            s0+=__shfl_xor_sync(0xffffffffu,s0,1); s0+=__shfl_xor_sync(0xffffffffu,s0,2);
            s1+=__shfl_xor_sync(0xffffffffu,s1,1); s1+=__shfl_xor_sync(0xffffffffu,s1,2);
            lrow[mi*2]  =lrow[mi*2]  *al[mi*2]  +s0;
            lrow[mi*2+1]=lrow[mi*2+1]*al[mi*2+1]+s1;
        }

        // P -> per-warp fragment buffers (proven R8 index pattern, per m-tile)
        #pragma unroll
        for(int mi=0;mi<2;mi++){
            unsigned* Pm = Pw + mi*1024;
            #pragma unroll
            for(int ni=0;ni<8;ni++){
                unsigned* pp=&Pm[(ni*32 + g*4 + ((2*tg)&3))*4 + 2*(tg>>1)];
                *(uint2*)pp    =make_uint2(f2tf(sc[mi][ni][0]), f2tf(sc[mi][ni][2]));
                *(uint2*)(pp+4)=make_uint2(f2tf(sc[mi][ni][1]), f2tf(sc[mi][ni][3]));
            }
        }
        __syncwarp();

        #pragma unroll
        for(int mi=0;mi<2;mi++)
            #pragma unroll
            for(int di=0;di<8;di++){
                oc[mi][di][0]*=al[mi*2];   oc[mi][di][1]*=al[mi*2];
                oc[mi][di][2]*=al[mi*2+1]; oc[mi][di][3]*=al[mi*2+1];
            }
        // O += P @ V
        #pragma unroll
        for(int ks=0;ks<8;ks++){
            const int k0=ks*8;
            uint4 af4[2];
            af4[0]=*(const uint4*)&Pw[         ks*128 + lane*4];
            af4[1]=*(const uint4*)&Pw[1024 +   ks*128 + lane*4];
            #pragma unroll
            for(int di=0;di<8;di++){
                unsigned bf[2];
                bf[0]=Vs[(k0+tg  )*FSTR+di*8+g];
                bf[1]=Vs[(k0+tg+4)*FSTR+di*8+g];
                mma8(oc[0][di],(const unsigned*)&af4[0],bf);
                mma8(oc[1][di],(const unsigned*)&af4[1],bf);
            }
        }
        __syncwarp();
    }

    #pragma unroll
    for(int mi=0;mi<2;mi++){
        const float i0=1.f/lrow[mi*2], i1=1.f/lrow[mi*2+1];
        const int r0=q0+qb+mi*16+g, r1=r0+8;
        unsigned* O0=&g_attn[((size_t)(b*SEQ)+r0)*DIMC + h*HDIM];
        unsigned* O1=&g_attn[((size_t)(b*SEQ)+r1)*DIMC + h*HDIM];
        #pragma unroll
        for(int di=0;di<8;di++){
            const int c=di*8+2*tg;
            *(uint2*)&O0[c]=make_uint2(f2tf(oc[mi][di][0]*i0), f2tf(oc[mi][di][1]*i0));
            *(uint2*)&O1[c]=make_uint2(f2tf(oc[mi][di][2]*i1), f2tf(oc[mi][di][3]*i1));
        }
    }
}

// ---------------------------------------------------------------------------
extern "C" void kernel_launch(void* const* d_in, const int* in_sizes, int n_in,
                              void* d_out, int out_size)
{
    const float* x     = (const float*)d_in[0];
    const float* Wqkv  = (const float*)d_in[1];
    const float* bqkv  = (const float*)d_in[2];
    const float* Wproj = (const float*)d_in[3];
    const float* bproj = (const float*)d_in[4];
    float* out = (float*)d_out;

    cudaFuncSetAttribute(flash_mma, cudaFuncAttributeMaxDynamicSharedMemorySize, FLASH_SMEM);

    unsigned *xtf, *wqkv, *wprj;
    cudaGetSymbolAddress((void**)&xtf,  g_xtf);
    cudaGetSymbolAddress((void**)&wqkv, g_wqkv);
    cudaGetSymbolAddress((void**)&wprj, g_wprj);

    cvt_tf32<<<(MTOT*DIMC/4+255)/256, 256>>>((const float4*)x,     (uint4*)xtf,  MTOT*DIMC/4);
    cvt_tf32<<<(DIMC*NQKV/4+255)/256, 256>>>((const float4*)Wqkv,  (uint4*)wqkv, DIMC*NQKV/4);
    cvt_tf32<<<(DIMC*DIMC/4+255)/256, 256>>>((const float4*)Wproj, (uint4*)wprj, DIMC*DIMC/4);

    dim3 g1(NQKV/128, MTOT/128);   // (24, 64)
    gemm_mma<NQKV, true><<<g1, 128>>>(xtf, wqkv, bqkv, nullptr);

    dim3 g2(SEQ/128, BATCH*NHEAD); // (16, 64)
    flash_mma<<<g2, 128, FLASH_SMEM>>>();

    dim3 g3(DIMC/128, MTOT/128);   // (8, 64)
    gemm_mma<DIMC, false><<<g3, 128>>>(nullptr, wprj, bproj, out);
}